// round 1
// baseline (speedup 1.0000x reference)
#include <cuda_runtime.h>
#include <math.h>
#include <stddef.h>

#define NPTS 1024
#define NBATCH 32
#define M_TOTAL (NBATCH * NPTS)

// ---------------- device scratch (static: no allocations allowed) ----------------
__device__ float g_Y1[NBATCH * 64 * NPTS];
__device__ float g_Y2[NBATCH * 64 * NPTS];
__device__ float g_Y3[NBATCH * 64 * NPTS];
__device__ float g_Y4[NBATCH * 128 * NPTS];
__device__ float g_Y5[NBATCH * 1024 * NPTS];
__device__ float g_Y6[NBATCH * 512 * NPTS];
__device__ float g_Y7[NBATCH * 256 * NPTS];
__device__ float g_Y8[NBATCH * 128 * NPTS];
__device__ float g_Y9[NBATCH * 128 * NPTS];
__device__ float g_gf[NBATCH * 1024];
__device__ float g_stats[2 * 9 * 1024];          // mean[9][1024], rstd[9][1024]
__device__ float g_Wt[2655744];                  // transposed weights (3*Cin*Cout per layer)
__device__ float g_bias[2371];                   // sum_i w[i][o][0] per layer

// ---------------- weight prep ----------------
__global__ void wprep_kernel(const float* __restrict__ w, float* __restrict__ Wt,
                             int Cin, int Cout) {
    int total = Cin * Cout;
    for (int idx = blockIdx.x * blockDim.x + threadIdx.x; idx < total;
         idx += gridDim.x * blockDim.x) {
        int i = idx / Cout;
        int o = idx - i * Cout;
        const float* wp = w + (size_t)idx * 4;   // (i*Cout+o)*4
        Wt[(size_t)(i * 3 + 0) * Cout + o] = wp[1];
        Wt[(size_t)(i * 3 + 1) * Cout + o] = wp[2];
        Wt[(size_t)(i * 3 + 2) * Cout + o] = wp[3];
    }
}

__global__ void bias_kernel(const float* __restrict__ w, float* __restrict__ bias,
                            int Cin, int Cout) {
    int o = blockIdx.x * blockDim.x + threadIdx.x;
    if (o < Cout) {
        float s = 0.f;
        for (int i = 0; i < Cin; ++i) s += w[(size_t)(i * Cout + o) * 4];
        bias[o] = s;
    }
}

// ---------------- BN stats: per-channel mean / rstd over B*N ----------------
__global__ void stats_kernel(const float* __restrict__ Y, float* __restrict__ mean,
                             float* __restrict__ rstd, int C) {
    int c = blockIdx.x;
    float s = 0.f, s2 = 0.f;
    for (int idx = threadIdx.x; idx < M_TOTAL; idx += 256) {
        int b = idx >> 10;
        int n = idx & 1023;
        float v = Y[(size_t)(b * C + c) * NPTS + n];
        s += v;
        s2 = fmaf(v, v, s2);
    }
    __shared__ float sh[256], sh2[256];
    sh[threadIdx.x] = s;
    sh2[threadIdx.x] = s2;
    __syncthreads();
    for (int off = 128; off > 0; off >>= 1) {
        if (threadIdx.x < off) {
            sh[threadIdx.x] += sh[threadIdx.x + off];
            sh2[threadIdx.x] += sh2[threadIdx.x + off];
        }
        __syncthreads();
    }
    if (threadIdx.x == 0) {
        float m = sh[0] * (1.f / (float)M_TOTAL);
        float var = sh2[0] * (1.f / (float)M_TOTAL) - m * m;
        mean[c] = m;
        rstd[c] = rsqrtf(var + 1e-5f);
    }
}

// ---------------- max over N then BN (BN is positive-affine: commutes with max) ----------------
__global__ void maxgf_kernel(const float* __restrict__ Y5, const float* __restrict__ mean,
                             const float* __restrict__ rstd, float* __restrict__ gf) {
    int idx = blockIdx.x * 8 + (threadIdx.x >> 5);   // (b,c) pair, 32768 total
    int lane = threadIdx.x & 31;
    int b = idx >> 10;
    int c = idx & 1023;
    const float* p = Y5 + (size_t)(b * 1024 + c) * NPTS;
    float mx = -3.402823466e38f;
    for (int n = lane; n < NPTS; n += 32) mx = fmaxf(mx, p[n]);
#pragma unroll
    for (int off = 16; off > 0; off >>= 1)
        mx = fmaxf(mx, __shfl_xor_sync(0xffffffffu, mx, off));
    if (lane == 0) gf[b * 1024 + c] = (mx - mean[c]) * rstd[c];
}

// ---------------- fused BN+tanh+Jacobi feature GEMM ----------------
// Y[b, o, n] = bias[o] + sum_{c,d in 1..3} P_d(tanh(bn(X[b,c,n]))) * Wt[(3c+d-1)*Cout+o]
template <int BNT, int TN, bool HAS_BN, bool CONCAT>
__global__ __launch_bounds__(256) void kan_gemm(
    const float* __restrict__ X, const float* __restrict__ mean,
    const float* __restrict__ rstd, const float* __restrict__ gf,
    const float* __restrict__ Wt, const float* __restrict__ bias,
    float* __restrict__ Y, int Cin, int Cout) {
    constexpr int BM = 128;   // points per block (one batch, 128 consecutive n)
    constexpr int KC = 8;     // channels per K chunk
    constexpr int KF = 24;    // features per K chunk (3 per channel)
    __shared__ float As[KF * BM];
    __shared__ float Ws[KF * BNT];

    const int tid = threadIdx.x;
    const int tx = tid & 15;    // row group: rows tx*8 .. tx*8+7
    const int ty = tid >> 4;    // col group: cols ty*TN .. ty*TN+TN-1
    const int b = blockIdx.x >> 3;
    const int n0 = (blockIdx.x & 7) * BM;
    const int o0 = blockIdx.y * BNT;

    float acc[TN][8];
#pragma unroll
    for (int j = 0; j < TN; ++j) {
        int o = o0 + ty * TN + j;
        float bz = (o < Cout) ? bias[o] : 0.f;
#pragma unroll
        for (int r = 0; r < 8; ++r) acc[j][r] = bz;
    }

    const int nChunks = (Cin + KC - 1) / KC;
    for (int ch = 0; ch < nChunks; ++ch) {
        int c0 = ch * KC;
        // generate feature tile: tanh + Jacobi polys (a=b=1, deg 3)
        for (int v = tid; v < BM * KC; v += 256) {
            int mm = v & (BM - 1);
            int cc = v >> 7;
            int c = c0 + cc;
            float p1 = 0.f, p2 = 0.f, p3 = 0.f;
            if (c < Cin) {
                float x;
                if (CONCAT) {
                    if (c < 64)
                        x = (X[(size_t)(b * 64 + c) * NPTS + n0 + mm] - mean[c]) * rstd[c];
                    else
                        x = gf[b * 1024 + (c - 64)];
                } else if (HAS_BN) {
                    x = (X[(size_t)(b * Cin + c) * NPTS + n0 + mm] - mean[c]) * rstd[c];
                } else {
                    x = X[(size_t)(b * Cin + c) * NPTS + n0 + mm];
                }
                float t = tanhf(x);
                p1 = 2.f * t;                          // (a-b+(a+b+2)t)/2
                p2 = fmaf(3.75f * t, t, -0.75f);       // 1.875t*p1 - 0.75
                p3 = fmaf((56.f / 30.f) * t, p2, -0.8f * p1);
            }
            As[(3 * cc + 0) * BM + mm] = p1;
            As[(3 * cc + 1) * BM + mm] = p2;
            As[(3 * cc + 2) * BM + mm] = p3;
        }
        // weight tile
        for (int v = tid; v < KF * BNT; v += 256) {
            int o = v & (BNT - 1);
            int k = v / BNT;
            int kk = c0 * 3 + k;
            int oo = o0 + o;
            Ws[k * BNT + o] = (kk < 3 * Cin && oo < Cout) ? Wt[(size_t)kk * Cout + oo] : 0.f;
        }
        __syncthreads();
#pragma unroll
        for (int k = 0; k < KF; ++k) {
            float a[8];
            float4 a0 = *reinterpret_cast<const float4*>(&As[k * BM + tx * 8]);
            float4 a1 = *reinterpret_cast<const float4*>(&As[k * BM + tx * 8 + 4]);
            a[0] = a0.x; a[1] = a0.y; a[2] = a0.z; a[3] = a0.w;
            a[4] = a1.x; a[5] = a1.y; a[6] = a1.z; a[7] = a1.w;
            float bv[TN];
#pragma unroll
            for (int j = 0; j < TN; j += 4) {
                float4 bq = *reinterpret_cast<const float4*>(&Ws[k * BNT + ty * TN + j]);
                bv[j] = bq.x; bv[j + 1] = bq.y; bv[j + 2] = bq.z; bv[j + 3] = bq.w;
            }
#pragma unroll
            for (int j = 0; j < TN; ++j)
#pragma unroll
                for (int r = 0; r < 8; ++r) acc[j][r] = fmaf(a[r], bv[j], acc[j][r]);
        }
        __syncthreads();
    }

#pragma unroll
    for (int j = 0; j < TN; ++j) {
        int o = o0 + ty * TN + j;
        if (o < Cout) {
            float* yp = Y + (size_t)(b * Cout + o) * NPTS + n0 + tx * 8;
            *reinterpret_cast<float4*>(yp) =
                make_float4(acc[j][0], acc[j][1], acc[j][2], acc[j][3]);
            *reinterpret_cast<float4*>(yp + 4) =
                make_float4(acc[j][4], acc[j][5], acc[j][6], acc[j][7]);
        }
    }
}

// ---------------- host launch ----------------
extern "C" void kernel_launch(void* const* d_in, const int* in_sizes, int n_in,
                              void* d_out, int out_size) {
    static const int CIN[10] = {2, 64, 64, 64, 128, 1088, 512, 256, 128, 128};
    static const int COUT[10] = {64, 64, 64, 128, 1024, 512, 256, 128, 128, 3};

    float* Y[9];
    cudaGetSymbolAddress((void**)&Y[0], g_Y1);
    cudaGetSymbolAddress((void**)&Y[1], g_Y2);
    cudaGetSymbolAddress((void**)&Y[2], g_Y3);
    cudaGetSymbolAddress((void**)&Y[3], g_Y4);
    cudaGetSymbolAddress((void**)&Y[4], g_Y5);
    cudaGetSymbolAddress((void**)&Y[5], g_Y6);
    cudaGetSymbolAddress((void**)&Y[6], g_Y7);
    cudaGetSymbolAddress((void**)&Y[7], g_Y8);
    cudaGetSymbolAddress((void**)&Y[8], g_Y9);
    float *Wt, *bias, *stats, *gfp;
    cudaGetSymbolAddress((void**)&Wt, g_Wt);
    cudaGetSymbolAddress((void**)&bias, g_bias);
    cudaGetSymbolAddress((void**)&stats, g_stats);
    cudaGetSymbolAddress((void**)&gfp, g_gf);

    const float* x = (const float*)d_in[0];
    const float* w[10];
    for (int i = 0; i < 10; ++i) w[i] = (const float*)d_in[1 + i];

    float* WtL[10];
    float* biasL[10];
    {
        size_t woff = 0, boff = 0;
        for (int l = 0; l < 10; ++l) {
            WtL[l] = Wt + woff;
            biasL[l] = bias + boff;
            woff += (size_t)3 * CIN[l] * COUT[l];
            boff += COUT[l];
        }
    }
    float* meanA = stats;
    float* rstdA = stats + 9 * 1024;
#define MEAN(l) (meanA + (l) * 1024)
#define RSTD(l) (rstdA + (l) * 1024)

    for (int l = 0; l < 10; ++l) {
        int total = CIN[l] * COUT[l];
        wprep_kernel<<<(total + 255) / 256, 256>>>(w[l], WtL[l], CIN[l], COUT[l]);
        bias_kernel<<<(COUT[l] + 255) / 256, 256>>>(w[l], biasL[l], CIN[l], COUT[l]);
    }

    // L1: x (no BN) -> Y1 (64)
    kan_gemm<64, 4, false, false><<<dim3(256, 1), 256>>>(
        x, nullptr, nullptr, nullptr, WtL[0], biasL[0], Y[0], 2, 64);
    stats_kernel<<<64, 256>>>(Y[0], MEAN(0), RSTD(0), 64);
    // L2 -> Y2 (64)
    kan_gemm<64, 4, true, false><<<dim3(256, 1), 256>>>(
        Y[0], MEAN(0), RSTD(0), nullptr, WtL[1], biasL[1], Y[1], 64, 64);
    stats_kernel<<<64, 256>>>(Y[1], MEAN(1), RSTD(1), 64);
    // L3 -> Y3 (64)
    kan_gemm<64, 4, true, false><<<dim3(256, 1), 256>>>(
        Y[1], MEAN(1), RSTD(1), nullptr, WtL[2], biasL[2], Y[2], 64, 64);
    stats_kernel<<<64, 256>>>(Y[2], MEAN(2), RSTD(2), 64);
    // L4 -> Y4 (128)
    kan_gemm<128, 8, true, false><<<dim3(256, 1), 256>>>(
        Y[2], MEAN(2), RSTD(2), nullptr, WtL[3], biasL[3], Y[3], 64, 128);
    stats_kernel<<<128, 256>>>(Y[3], MEAN(3), RSTD(3), 128);
    // L5 -> Y5 (1024)
    kan_gemm<128, 8, true, false><<<dim3(256, 8), 256>>>(
        Y[3], MEAN(3), RSTD(3), nullptr, WtL[4], biasL[4], Y[4], 128, 1024);
    stats_kernel<<<1024, 256>>>(Y[4], MEAN(4), RSTD(4), 1024);
    // global feature: max over n of BN(Y5)
    maxgf_kernel<<<4096, 256>>>(Y[4], MEAN(4), RSTD(4), gfp);
    // L6: concat(BN(Y2), gf) -> Y6 (512)
    kan_gemm<128, 8, true, true><<<dim3(256, 4), 256>>>(
        Y[1], MEAN(1), RSTD(1), gfp, WtL[5], biasL[5], Y[5], 1088, 512);
    stats_kernel<<<512, 256>>>(Y[5], MEAN(5), RSTD(5), 512);
    // L7 -> Y7 (256)
    kan_gemm<128, 8, true, false><<<dim3(256, 2), 256>>>(
        Y[5], MEAN(5), RSTD(5), nullptr, WtL[6], biasL[6], Y[6], 512, 256);
    stats_kernel<<<256, 256>>>(Y[6], MEAN(6), RSTD(6), 256);
    // L8 -> Y8 (128)
    kan_gemm<128, 8, true, false><<<dim3(256, 1), 256>>>(
        Y[6], MEAN(6), RSTD(6), nullptr, WtL[7], biasL[7], Y[7], 256, 128);
    stats_kernel<<<128, 256>>>(Y[7], MEAN(7), RSTD(7), 128);
    // L9 -> Y9 (128)
    kan_gemm<128, 8, true, false><<<dim3(256, 1), 256>>>(
        Y[7], MEAN(7), RSTD(7), nullptr, WtL[8], biasL[8], Y[8], 128, 128);
    stats_kernel<<<128, 256>>>(Y[8], MEAN(8), RSTD(8), 128);
    // L10: -> d_out (3), no BN after
    kan_gemm<64, 4, true, false><<<dim3(256, 1), 256>>>(
        Y[8], MEAN(8), RSTD(8), nullptr, WtL[9], biasL[9], (float*)d_out, 128, 3);
#undef MEAN
#undef RSTD
}